// round 3
// baseline (speedup 1.0000x reference)
#include <cuda_runtime.h>
#include <math.h>

#define B_ 4
#define T_ 8
#define N_ 1024
#define FI_ 64
#define FO_ 64
#define ALPHA_ 0.2f

#define JT 256          // j-tile per chunk
#define RT 128          // rows per block in k_att
#define CAP 128         // per-warp compacted list capacity

// -------- device scratch (static: no allocations allowed) --------
__device__ float g_hm[B_*T_*N_*FO_];   // h * m_j   (8 MB)
__device__ float g_s1[B_*T_*N_];
__device__ float g_s2[B_*T_*N_];
__device__ int   g_maxs2e;             // monotone-encoded fp32 max of s2

// monotone float->int encoding for atomicMax
__device__ __forceinline__ int enc_f(float f) {
    int e = __float_as_int(f);
    return (e < 0) ? (e ^ 0x7fffffff) : e;
}
__device__ __forceinline__ float dec_f(int e) {
    if (e < 0) e ^= 0x7fffffff;
    return __int_as_float(e);
}

__global__ void k_init() {
    g_maxs2e = (int)0x80000000;  // -inf under encoding
}

// -------- kernel 1: h = inp@W, s1, s2, hm = h*m, global max(s2) --------
__global__ __launch_bounds__(256) void k_pre(
    const float* __restrict__ inp,
    const float* __restrict__ att_mask,
    const float* __restrict__ W,
    const float* __restrict__ a)
{
    __shared__ float Ws[64*64];     // [f][o]
    __shared__ float Is[64*68];     // [r][f], padded to 68 (bank-conflict-free, 16B aligned rows)
    __shared__ float As[128];

    const int tid = threadIdx.x;
    const int gr0 = blockIdx.x * 64;

    // stage W (coalesced float4)
    {
        const float4* W4 = (const float4*)W;
        float4* Ws4 = (float4*)Ws;
        #pragma unroll
        for (int idx = tid; idx < 1024; idx += 256) Ws4[idx] = W4[idx];
    }
    // stage 64 input rows (contiguous in gmem), padded layout in smem
    {
        const float4* I4 = (const float4*)(inp + (size_t)gr0 * 64);
        float4* Is4 = (float4*)Is;
        #pragma unroll
        for (int idx = tid; idx < 1024; idx += 256) {
            int r = idx >> 4, q = idx & 15;
            Is4[r * 17 + q] = I4[idx];
        }
    }
    if (tid < 128) As[tid] = a[tid];
    __syncthreads();

    const int r  = tid >> 2;        // 0..63  (row within block)
    const int oq = tid & 3;         // 0..3   (16-output segment)
    const int o0 = oq * 16;

    float acc[16];
    #pragma unroll
    for (int k = 0; k < 16; k++) acc[k] = 0.f;

    #pragma unroll 4
    for (int f = 0; f < 64; f++) {
        float x = Is[r * 68 + f];
        #pragma unroll
        for (int k = 0; k < 16; k++)
            acc[k] = fmaf(x, Ws[f * 64 + o0 + k], acc[k]);
    }

    // attention score partials
    float p1 = 0.f, p2 = 0.f;
    #pragma unroll
    for (int k = 0; k < 16; k++) {
        p1 = fmaf(acc[k], As[o0 + k],      p1);
        p2 = fmaf(acc[k], As[64 + o0 + k], p2);
    }
    // reduce across the 4 threads of this row (lanes 4r..4r+3, aligned groups)
    p1 += __shfl_xor_sync(0xffffffffu, p1, 1);
    p1 += __shfl_xor_sync(0xffffffffu, p1, 2);
    p2 += __shfl_xor_sync(0xffffffffu, p2, 1);
    p2 += __shfl_xor_sync(0xffffffffu, p2, 2);

    const int gr = gr0 + r;
    const int b = gr >> 13;            // / (T*N)
    const int t = (gr >> 10) & 7;
    const int n = gr & 1023;

    const float m = att_mask[b * (N_ * T_) + n * T_ + t];

    // store hm = h * m (coalesced float4)
    #pragma unroll
    for (int k = 0; k < 16; k += 4) {
        float4 v = make_float4(acc[k] * m, acc[k+1] * m, acc[k+2] * m, acc[k+3] * m);
        *(float4*)(g_hm + (size_t)gr * 64 + o0 + k) = v;
    }

    if (oq == 0) { g_s1[gr] = p1; g_s2[gr] = p2; }

    // warp-level max(s2) -> one atomic per warp
    float ms = (oq == 0) ? p2 : -3.0e38f;
    #pragma unroll
    for (int off = 16; off; off >>= 1)
        ms = fmaxf(ms, __shfl_xor_sync(0xffffffffu, ms, off));
    if ((tid & 31) == 0)
        atomicMax(&g_maxs2e, enc_f(ms));
}

// -------- kernel 2: fused sparse softmax-attention + output --------
// grid: (N/RT, T, B), block 256, dynamic smem
#define SM_HM   0                       // float[JT*64]           65536
#define SM_ACC  (SM_HM + JT*64*4)       // float[RT*64]           32768
#define SM_WS   (SM_ACC + RT*64*4)      // float[8*CAP]            4096
#define SM_JS   (SM_WS + 8*CAP*4)       // int[8*CAP]              4096
#define SM_S2   (SM_JS + 8*CAP*4)       // float[JT]               1024
#define SM_S1   (SM_S2 + JT*4)          // float[RT]                512
#define SM_M    (SM_S1 + RT*4)          // float[RT]                512
#define SM_DEN  (SM_M  + RT*4)          // float[RT]                512
#define SM_TOT  (SM_DEN + RT*4)         // = 109056 bytes

__global__ __launch_bounds__(256) void k_att(
    const float* __restrict__ adj,
    const float* __restrict__ att_mask,
    float* __restrict__ out)
{
    extern __shared__ char sraw[];
    float* hm_s  = (float*)(sraw + SM_HM);
    float* acc_s = (float*)(sraw + SM_ACC);
    float* ws_s  = (float*)(sraw + SM_WS);
    int*   js_s  = (int*)  (sraw + SM_JS);
    float* s2_s  = (float*)(sraw + SM_S2);
    float* s1_s  = (float*)(sraw + SM_S1);
    float* m_s   = (float*)(sraw + SM_M);
    float* den_s = (float*)(sraw + SM_DEN);

    const int tid  = threadIdx.x;
    const int lane = tid & 31;
    const int warp = tid >> 5;
    const int rg = blockIdx.x, t = blockIdx.y, b = blockIdx.z;
    const int bt = b * T_ + t;
    const int i0 = rg * RT;

    const float maxS2 = dec_f(g_maxs2e);

    for (int idx = tid; idx < RT * 64; idx += 256) acc_s[idx] = 0.f;
    for (int idx = tid; idx < RT; idx += 256) {
        den_s[idx] = 0.f;
        s1_s[idx] = g_s1[bt * N_ + i0 + idx];
        m_s[idx]  = att_mask[b * (N_ * T_) + (i0 + idx) * T_ + t];
    }

    float* wsw = ws_s + warp * CAP;
    int*   jsw = js_s + warp * CAP;
    const unsigned lmlt = (1u << lane) - 1u;
    const float2* hm2 = (const float2*)hm_s;

    for (int chunk = 0; chunk < N_ / JT; chunk++) {
        __syncthreads();
        // stage hm tile + s2 tile
        {
            const float4* src = (const float4*)(g_hm + ((size_t)bt * N_ + chunk * JT) * 64);
            float4* dst = (float4*)hm_s;
            #pragma unroll
            for (int idx = tid; idx < JT * 16; idx += 256) dst[idx] = src[idx];
            for (int idx = tid; idx < JT; idx += 256)
                s2_s[idx] = g_s2[bt * N_ + chunk * JT + idx];
        }
        __syncthreads();

        for (int rr = 0; rr < RT / 8; rr++) {
            const int r = warp * (RT / 8) + rr;
            const int i = i0 + r;
            const float s1v = s1_s[r];
            const float Mh = fmaxf(0.f, s1v + maxS2);
            const float* arow = adj + ((size_t)t * N_ + i) * N_ + chunk * JT;

            float av[JT / 32];
            #pragma unroll
            for (int k = 0; k < JT / 32; k++) av[k] = __ldg(arow + k * 32 + lane);

            float acc0 = 0.f, acc1 = 0.f, dsum = 0.f;
            int cur = 0;

            #pragma unroll
            for (int k = 0; k < JT / 32; k++) {
                const int jl = k * 32 + lane;
                const float x = s1v + s2_s[jl];
                const float ev = (x > 0.f) ? x : ALPHA_ * x;
                const bool nz = av[k] > 0.f;
                float w = 0.f;
                if (nz) w = __expf(fmaf(ev, av[k], -Mh));
                dsum += w;
                const unsigned ball = __ballot_sync(0xffffffffu, nz);
                const int pos = cur + __popc(ball & lmlt);
                if (nz) { wsw[pos] = w; jsw[pos] = jl; }
                cur += __popc(ball);
                if (cur >= CAP - 32) {           // warp-uniform flush
                    __syncwarp();
                    #pragma unroll 4
                    for (int kk = 0; kk < cur; kk++) {
                        const float wv = wsw[kk];
                        const float2 v = hm2[jsw[kk] * 32 + lane];
                        acc0 = fmaf(wv, v.x, acc0);
                        acc1 = fmaf(wv, v.y, acc1);
                    }
                    cur = 0;
                    __syncwarp();
                }
            }
            __syncwarp();
            #pragma unroll 4
            for (int kk = 0; kk < cur; kk++) {
                const float wv = wsw[kk];
                const float2 v = hm2[jsw[kk] * 32 + lane];
                acc0 = fmaf(wv, v.x, acc0);
                acc1 = fmaf(wv, v.y, acc1);
            }
            __syncwarp();

            #pragma unroll
            for (int off = 16; off; off >>= 1)
                dsum += __shfl_xor_sync(0xffffffffu, dsum, off);

            float2* ap = ((float2*)acc_s) + r * 32 + lane;
            float2 a2 = *ap;
            a2.x += acc0; a2.y += acc1;
            *ap = a2;
            if (lane == 0) den_s[r] += dsum;
        }
    }

    __syncthreads();
    // epilogue: out = elu(m_i * acc / denom), uniform fallback for all-masked rows
    for (int idx = tid; idx < RT * 64; idx += 256) {
        const int r = idx >> 6, o = idx & 63;
        const float d  = den_s[r];
        const float mi = m_s[r];
        float x;
        if (d > 0.f) {
            x = mi * acc_s[idx] / d;
        } else {
            // reference: softmax of all -1e12 row -> uniform 1/N
            float cs = 0.f;
            const float* hp = g_hm + (size_t)bt * N_ * 64 + o;
            for (int j = 0; j < N_; j++) cs += hp[j * 64];
            x = mi * cs * (1.f / N_);
        }
        out[((size_t)bt * N_ + i0 + r) * 64 + o] = (x > 0.f) ? x : expm1f(x);
    }
}

extern "C" void kernel_launch(void* const* d_in, const int* in_sizes, int n_in,
                              void* d_out, int out_size) {
    const float* adj      = (const float*)d_in[0];
    const float* inp      = (const float*)d_in[1];
    const float* att_mask = (const float*)d_in[2];
    const float* W        = (const float*)d_in[3];
    const float* a        = (const float*)d_in[4];
    float* out = (float*)d_out;

    // idempotent, called every time (no static guards)
    cudaFuncSetAttribute(k_att, cudaFuncAttributeMaxDynamicSharedMemorySize, SM_TOT);

    k_init<<<1, 1>>>();
    k_pre<<<(B_ * T_ * N_) / 64, 256>>>(inp, att_mask, W, a);
    k_att<<<dim3(N_ / RT, T_, B_), 256, SM_TOT>>>(adj, att_mask, out);
}